// round 15
// baseline (speedup 1.0000x reference)
#include <cuda_runtime.h>
#include <cstdint>

#define TB      64
#define THREADS 256
#define HID     128
#define TSTEPS  28
#define INP     28
#define BATCH   8192
#define KA      156     // INP+HID concat k (layer 0, fused)
#define TBP     66      // Ak row pad (even; ≡2 mod 32 -> conflict-free LDS/STS.64)
#define NJP     64      // j-pairs

// layer-0 output sequence, transposed: [t][h][B]
__device__ __align__(16) float g_out0[(size_t)TSTEPS * HID * BATCH];
// layer-1 precomputed input GEMM, acc-packed: [t][jp][B][2]
__device__ __align__(16) float g_xw1[(size_t)TSTEPS * NJP * BATCH * 2];

typedef unsigned long long u64;

__device__ __forceinline__ u64 pack_dup(float a) {
    u64 r; asm("mov.b64 %0, {%1, %1};" : "=l"(r) : "r"(__float_as_uint(a))); return r;
}
__device__ __forceinline__ u64 pack_pair(float lo, float hi) {
    u64 r; asm("mov.b64 %0, {%1, %2};" : "=l"(r) : "r"(__float_as_uint(lo)), "r"(__float_as_uint(hi))); return r;
}
__device__ __forceinline__ void ffma2(u64& d, u64 a, u64 b) {
    asm("fma.rn.f32x2 %0, %1, %2, %0;" : "+l"(d) : "l"(a), "l"(b));
}
__device__ __forceinline__ float lo2(u64 v) { return __uint_as_float((unsigned)v); }
__device__ __forceinline__ float hi2(u64 v) { return __uint_as_float((unsigned)(v >> 32)); }

__device__ __forceinline__ float fast_tanh(float x) {
    float e = __expf(2.0f * x);
    return 1.0f - __fdividef(2.0f, e + 1.0f);
}

extern __shared__ float smem[];

// per-k: 1 LDS.64 (A b-pair) + 4 warp-uniform LDS.128 (w) + 16 FFMA2
#define GEMM_LOOP(KK)                                                           \
    _Pragma("unroll 4")                                                         \
    for (int k = 0; k < KK; ++k) {                                              \
        u64 ap = *reinterpret_cast<const u64*>(akp); akp += TBP;                \
        u64 A0 = pack_dup(lo2(ap));                                             \
        u64 A1 = pack_dup(hi2(ap));                                             \
        ulonglong2 w0 = *reinterpret_cast<const ulonglong2*>(wkp);              \
        ulonglong2 w1 = *reinterpret_cast<const ulonglong2*>(wkp + 4);          \
        ulonglong2 w2 = *reinterpret_cast<const ulonglong2*>(wkp + 8);          \
        ulonglong2 w3 = *reinterpret_cast<const ulonglong2*>(wkp + 12);         \
        wkp += HID;                                                             \
        ffma2(acc[0][0], A0, w0.x); ffma2(acc[0][1], A0, w0.y);                 \
        ffma2(acc[0][2], A0, w1.x); ffma2(acc[0][3], A0, w1.y);                 \
        ffma2(acc[0][4], A0, w2.x); ffma2(acc[0][5], A0, w2.y);                 \
        ffma2(acc[0][6], A0, w3.x); ffma2(acc[0][7], A0, w3.y);                 \
        ffma2(acc[1][0], A1, w0.x); ffma2(acc[1][1], A1, w0.y);                 \
        ffma2(acc[1][2], A1, w1.x); ffma2(acc[1][3], A1, w1.y);                 \
        ffma2(acc[1][4], A1, w2.x); ffma2(acc[1][5], A1, w2.y);                 \
        ffma2(acc[1][6], A1, w3.x); ffma2(acc[1][7], A1, w3.y);                 \
    }

// ================= K2: layer 0 (fused input GEMM + recurrence) =================
__global__ void __launch_bounds__(THREADS, 1)
rnn_layer0(const float* __restrict__ x,
           const float* __restrict__ Wih0, const float* __restrict__ Whh0,
           const float* __restrict__ bih0, const float* __restrict__ bhh0)
{
    float* Wsm = smem;                 // [KA][HID]
    float* Ak  = Wsm + KA * HID;       // [KA][TBP]: rows 0..27 = x_t, 28..155 = h
    float* b0s = Ak + KA * TBP;        // HID

    const int tid = threadIdx.x;
    const int B0  = blockIdx.x * TB;

    for (int d = tid; d < KA * HID; d += THREADS) {
        int k = d >> 7, j = d & 127;
        Wsm[k * HID + j] = (k < INP) ? Wih0[j * INP + k] : Whh0[j * HID + (k - INP)];
    }
    for (int j = tid; j < HID; j += THREADS) b0s[j] = bih0[j] + bhh0[j];
    for (int d = tid; d < HID * TB; d += THREADS)       // h0 = 0
        Ak[(INP + (d >> 6)) * TBP + (d & 63)] = 0.0f;
    __syncthreads();

    const int wid = tid >> 5, lane = tid & 31;
    const int j0 = wid * 16;
    const float* wbase = Wsm + j0;
    const float* abase = Ak + 2 * lane;

    for (int t = 0; t < TSTEPS; ++t) {
        for (int d = tid; d < TB * 32; d += THREADS) {   // stage x[:,t,:] -> Ak[i][b]
            int i = d & 31, b = d >> 5;
            if (i < INP)
                Ak[i * TBP + b] = x[(size_t)(B0 + b) * (TSTEPS * INP) + t * INP + i];
        }
        __syncthreads();   // stage + prev-step h visible

        u64 acc[2][8];
        #pragma unroll
        for (int jp = 0; jp < 8; ++jp) {
            u64 bb = pack_pair(b0s[j0 + 2*jp], b0s[j0 + 2*jp + 1]);
            acc[0][jp] = bb; acc[1][jp] = bb;
        }
        const float* akp = abase;
        const float* wkp = wbase;
        GEMM_LOOP(KA)
        __syncthreads();   // all h reads done before overwrite

        // epilogue: tanh -> Ak h rows (STS.64) + g_out0[t][j][B] (coalesced STG.64)
        #pragma unroll
        for (int jp = 0; jp < 8; ++jp) {
            float v00 = fast_tanh(lo2(acc[0][jp]));   // (b0, j)
            float v01 = fast_tanh(hi2(acc[0][jp]));   // (b0, j+1)
            float v10 = fast_tanh(lo2(acc[1][jp]));   // (b1, j)
            float v11 = fast_tanh(hi2(acc[1][jp]));
            int j = j0 + 2 * jp;
            u64 pj  = pack_pair(v00, v10);            // (b0,b1) for row j
            u64 pj1 = pack_pair(v01, v11);            // for row j+1
            *reinterpret_cast<u64*>(&Ak[(INP + j)     * TBP + 2*lane]) = pj;
            *reinterpret_cast<u64*>(&Ak[(INP + j + 1) * TBP + 2*lane]) = pj1;
            *reinterpret_cast<u64*>(&g_out0[((size_t)t * HID + j)     * BATCH + B0 + 2*lane]) = pj;
            *reinterpret_cast<u64*>(&g_out0[((size_t)t * HID + j + 1) * BATCH + B0 + 2*lane]) = pj1;
        }
        // next iteration's pre-GEMM sync publishes h(t)
    }
}

// ================= K3: layer-1 input GEMM (parallel over t) =================
// xw1[t][jp][b][2] = bias1 + out0[t][b][:] . Wih1^T   (acc-packed for K4)
__global__ void __launch_bounds__(THREADS, 2)
gemm_in1(const float* __restrict__ Wih1,
         const float* __restrict__ bih1, const float* __restrict__ bhh1)
{
    float* Wsm = smem;                 // [HID][HID]  Wsm[k][j] = Wih1[j][k]
    float* Ak  = Wsm + HID * HID;      // [HID][TBP]
    float* b1s = Ak + HID * TBP;       // HID

    const int tid = threadIdx.x;
    const int B0  = blockIdx.x * TB;
    const int t   = blockIdx.y;

    for (int d = tid; d < HID * HID; d += THREADS) {
        int k = d >> 7, j = d & 127;
        Wsm[k * HID + j] = Wih1[j * HID + k];
    }
    for (int j = tid; j < HID; j += THREADS) b1s[j] = bih1[j] + bhh1[j];
    // stage out0[t][h][B0..B0+63] -> Ak[h][b]   (coalesced u64 copy)
    for (int d = tid; d < HID * 32; d += THREADS) {
        int h = d >> 5, q = d & 31;
        *reinterpret_cast<u64*>(&Ak[h * TBP + 2 * q]) =
            *reinterpret_cast<const u64*>(&g_out0[((size_t)t * HID + h) * BATCH + B0 + 2 * q]);
    }
    __syncthreads();

    const int wid = tid >> 5, lane = tid & 31;
    const int j0 = wid * 16;

    u64 acc[2][8];
    #pragma unroll
    for (int jp = 0; jp < 8; ++jp) {
        u64 bb = pack_pair(b1s[j0 + 2*jp], b1s[j0 + 2*jp + 1]);
        acc[0][jp] = bb; acc[1][jp] = bb;
    }
    const float* akp = Ak + 2 * lane;
    const float* wkp = Wsm + j0;
    GEMM_LOOP(HID)

    // store acc-packed: 8 coalesced STG.128
    #pragma unroll
    for (int jp = 0; jp < 8; ++jp) {
        int jpg = (j0 >> 1) + jp;
        ulonglong2 v; v.x = acc[0][jp]; v.y = acc[1][jp];
        *reinterpret_cast<ulonglong2*>(
            &g_xw1[(((size_t)t * NJP + jpg) * BATCH + B0 + 2 * lane) * 2]) = v;
    }
}

// ================= K4: layer-1 recurrence + FC head =================
__global__ void __launch_bounds__(THREADS, 1)
rnn_layer1_fc(const float* __restrict__ Whh1,
              const float* __restrict__ fcw, const float* __restrict__ fcb,
              float* __restrict__ out)
{
    float* Wsm  = smem;                 // [HID][HID]  Wsm[k][j] = Whh1[j][k]
    float* Ak   = Wsm + HID * HID;      // [HID][TBP]  h rows
    float* fcs  = Ak + HID * TBP;       // 10*HID
    float* fcbs = fcs + 10 * HID;       // 16

    const int tid = threadIdx.x;
    const int B0  = blockIdx.x * TB;

    for (int d = tid; d < HID * HID; d += THREADS) {
        int k = d >> 7, j = d & 127;
        Wsm[k * HID + j] = Whh1[j * HID + k];
    }
    for (int d = tid; d < 10 * HID; d += THREADS) fcs[d] = fcw[d];
    if (tid < 10) fcbs[tid] = fcb[tid];
    for (int d = tid; d < HID * TB; d += THREADS)       // h0 = 0
        Ak[(d >> 6) * TBP + (d & 63)] = 0.0f;
    __syncthreads();

    const int wid = tid >> 5, lane = tid & 31;
    const int j0 = wid * 16;
    const float* wbase = Wsm + j0;
    const float* abase = Ak + 2 * lane;

    // prefetch xw1 for t=0
    ulonglong2 pf[8];
    #pragma unroll
    for (int jp = 0; jp < 8; ++jp) {
        int jpg = (j0 >> 1) + jp;
        pf[jp] = *reinterpret_cast<const ulonglong2*>(
            &g_xw1[(((size_t)0 * NJP + jpg) * BATCH + B0 + 2 * lane) * 2]);
    }

    for (int t = 0; t < TSTEPS; ++t) {
        u64 acc[2][8];
        #pragma unroll
        for (int jp = 0; jp < 8; ++jp) { acc[0][jp] = pf[jp].x; acc[1][jp] = pf[jp].y; }
        // prefetch next t (uniform branch; hidden under the k-loop)
        if (t + 1 < TSTEPS) {
            #pragma unroll
            for (int jp = 0; jp < 8; ++jp) {
                int jpg = (j0 >> 1) + jp;
                pf[jp] = *reinterpret_cast<const ulonglong2*>(
                    &g_xw1[(((size_t)(t + 1) * NJP + jpg) * BATCH + B0 + 2 * lane) * 2]);
            }
        }

        const float* akp = abase;
        const float* wkp = wbase;
        GEMM_LOOP(HID)
        __syncthreads();   // all h(t-1) reads done

        #pragma unroll
        for (int jp = 0; jp < 8; ++jp) {
            float v00 = fast_tanh(lo2(acc[0][jp]));
            float v01 = fast_tanh(hi2(acc[0][jp]));
            float v10 = fast_tanh(lo2(acc[1][jp]));
            float v11 = fast_tanh(hi2(acc[1][jp]));
            int j = j0 + 2 * jp;
            *reinterpret_cast<u64*>(&Ak[j       * TBP + 2*lane]) = pack_pair(v00, v10);
            *reinterpret_cast<u64*>(&Ak[(j + 1) * TBP + 2*lane]) = pack_pair(v01, v11);
        }
        __syncthreads();   // h(t) visible before next k-loop / FC
    }

    // FC head: 640 outputs
    for (int o = tid; o < TB * 10; o += THREADS) {
        int b = o / 10, c = o - b * 10;
        const float* wv = &fcs[c * HID];
        float s = fcbs[c];
        #pragma unroll 8
        for (int k = 0; k < HID; ++k)
            s = fmaf(Ak[k * TBP + b], wv[k], s);
        out[(size_t)(B0 + b) * 10 + c] = s;
    }
}

extern "C" void kernel_launch(void* const* d_in, const int* in_sizes, int n_in,
                              void* d_out, int out_size) {
    const float* x     = (const float*)d_in[0];
    const float* Wih0  = (const float*)d_in[1];
    const float* Whh0  = (const float*)d_in[2];
    const float* bih0  = (const float*)d_in[3];
    const float* bhh0  = (const float*)d_in[4];
    const float* Wih1  = (const float*)d_in[5];
    const float* Whh1  = (const float*)d_in[6];
    const float* bih1  = (const float*)d_in[7];
    const float* bhh1  = (const float*)d_in[8];
    const float* fcw   = (const float*)d_in[9];
    const float* fcb   = (const float*)d_in[10];
    float* out = (float*)d_out;

    const int smemA = (KA * HID + KA * TBP + HID) * 4;                     // ~119 KB
    const int smemG = (HID * HID + HID * TBP + HID) * 4;                   // ~98 KB (2 CTA/SM)
    const int smemR = (HID * HID + HID * TBP + 10 * HID + 16) * 4;         // ~102 KB
    cudaFuncSetAttribute(rnn_layer0,    cudaFuncAttributeMaxDynamicSharedMemorySize, smemA);
    cudaFuncSetAttribute(gemm_in1,      cudaFuncAttributeMaxDynamicSharedMemorySize, smemG);
    cudaFuncSetAttribute(rnn_layer1_fc, cudaFuncAttributeMaxDynamicSharedMemorySize, smemR);

    const int gridB = BATCH / TB;   // 128
    rnn_layer0<<<gridB, THREADS, smemA>>>(x, Wih0, Whh0, bih0, bhh0);
    dim3 g3(gridB, TSTEPS);         // 128 x 28 = 3584 CTAs, 2 per SM
    gemm_in1<<<g3, THREADS, smemG>>>(Wih1, bih1, bhh1);
    rnn_layer1_fc<<<gridB, THREADS, smemR>>>(Whh1, fcw, fcb, out);
}

// round 16
// speedup vs baseline: 1.3108x; 1.3108x over previous
#include <cuda_runtime.h>
#include <cstdint>

#define TB      64
#define HID     128
#define TSTEPS  28
#define INP     28
#define BATCH   8192
#define TBP     66      // Ak row pad (≡2 mod 32 -> conflict-free LDS/STS.64)
#define WPAD    132     // weight row pad (≡4 mod 32 -> 4-way STS on transpose; rows 16B-aligned)
#define NJP     64      // j-pairs

// acc-packed interchange buffers: [t][jp][B][2]
__device__ __align__(16) float g_xw0 [(size_t)TSTEPS * NJP * BATCH * 2];
__device__ __align__(16) float g_out0[(size_t)TSTEPS * NJP * BATCH * 2];
__device__ __align__(16) float g_xw1 [(size_t)TSTEPS * NJP * BATCH * 2];

typedef unsigned long long u64;

__device__ __forceinline__ u64 pack_dup(float a) {
    u64 r; asm("mov.b64 %0, {%1, %1};" : "=l"(r) : "r"(__float_as_uint(a))); return r;
}
__device__ __forceinline__ u64 pack_pair(float lo, float hi) {
    u64 r; asm("mov.b64 %0, {%1, %2};" : "=l"(r) : "r"(__float_as_uint(lo)), "r"(__float_as_uint(hi))); return r;
}
__device__ __forceinline__ void ffma2(u64& d, u64 a, u64 b) {
    asm("fma.rn.f32x2 %0, %1, %2, %0;" : "+l"(d) : "l"(a), "l"(b));
}
__device__ __forceinline__ float lo2(u64 v) { return __uint_as_float((unsigned)v); }
__device__ __forceinline__ float hi2(u64 v) { return __uint_as_float((unsigned)(v >> 32)); }

__device__ __forceinline__ float fast_tanh(float x) {
    float e = __expf(2.0f * x);
    return 1.0f - __fdividef(2.0f, e + 1.0f);
}

extern __shared__ float smem[];

// 16-j warps (8 warps, 256 thr): per k 1 LDS.64 + 4 uniform LDS.128 + 16 FFMA2
#define GEMM16(KK, UNR)                                                         \
    _Pragma(UNR)                                                                \
    for (int k = 0; k < KK; ++k) {                                              \
        u64 ap = *reinterpret_cast<const u64*>(akp); akp += TBP;                \
        u64 A0 = pack_dup(lo2(ap));                                             \
        u64 A1 = pack_dup(hi2(ap));                                             \
        ulonglong2 w0 = *reinterpret_cast<const ulonglong2*>(wkp);              \
        ulonglong2 w1 = *reinterpret_cast<const ulonglong2*>(wkp + 4);          \
        ulonglong2 w2 = *reinterpret_cast<const ulonglong2*>(wkp + 8);          \
        ulonglong2 w3 = *reinterpret_cast<const ulonglong2*>(wkp + 12);         \
        wkp += WPAD;                                                            \
        ffma2(acc[0][0], A0, w0.x); ffma2(acc[0][1], A0, w0.y);                 \
        ffma2(acc[0][2], A0, w1.x); ffma2(acc[0][3], A0, w1.y);                 \
        ffma2(acc[0][4], A0, w2.x); ffma2(acc[0][5], A0, w2.y);                 \
        ffma2(acc[0][6], A0, w3.x); ffma2(acc[0][7], A0, w3.y);                 \
        ffma2(acc[1][0], A1, w0.x); ffma2(acc[1][1], A1, w0.y);                 \
        ffma2(acc[1][2], A1, w1.x); ffma2(acc[1][3], A1, w1.y);                 \
        ffma2(acc[1][4], A1, w2.x); ffma2(acc[1][5], A1, w2.y);                 \
        ffma2(acc[1][6], A1, w3.x); ffma2(acc[1][7], A1, w3.y);                 \
    }

// ============ K1: xw0 = x . Wih0^T + (bih0+bhh0), parallel over t ============
__global__ void __launch_bounds__(256)
k_ingemm0(const float* __restrict__ x, const float* __restrict__ Wih0,
          const float* __restrict__ bih0, const float* __restrict__ bhh0)
{
    float* Wsm = smem;                 // [INP][WPAD]
    float* bs  = Wsm + INP * WPAD;     // HID

    const int tid = threadIdx.x;
    const int B0  = blockIdx.x * TB;

    for (int d = tid; d < HID * INP; d += 256) {
        int j = d / INP, k = d - j * INP;
        Wsm[k * WPAD + j] = Wih0[d];
    }
    for (int j = tid; j < HID; j += 256) bs[j] = bih0[j] + bhh0[j];
    __syncthreads();

    const int wid = tid >> 5, lane = tid & 31;
    const int j0 = wid * 16;

    for (int tt = 0; tt < 7; ++tt) {
        const int t = blockIdx.y * 7 + tt;
        // x rows for this thread's b-pair, in registers (contiguous 112B each)
        float xr0[INP], xr1[INP];
        const float* xp0 = x + (size_t)(B0 + 2 * lane) * (TSTEPS * INP) + t * INP;
        const float* xp1 = xp0 + TSTEPS * INP;
        #pragma unroll
        for (int i = 0; i < INP; ++i) { xr0[i] = xp0[i]; xr1[i] = xp1[i]; }

        u64 acc[2][8];
        #pragma unroll
        for (int jp = 0; jp < 8; ++jp) {
            u64 bb = pack_pair(bs[j0 + 2*jp], bs[j0 + 2*jp + 1]);
            acc[0][jp] = bb; acc[1][jp] = bb;
        }
        const float* wkp = Wsm + j0;
        #pragma unroll
        for (int k = 0; k < INP; ++k) {
            u64 A0 = pack_dup(xr0[k]);
            u64 A1 = pack_dup(xr1[k]);
            ulonglong2 w0 = *reinterpret_cast<const ulonglong2*>(wkp);
            ulonglong2 w1 = *reinterpret_cast<const ulonglong2*>(wkp + 4);
            ulonglong2 w2 = *reinterpret_cast<const ulonglong2*>(wkp + 8);
            ulonglong2 w3 = *reinterpret_cast<const ulonglong2*>(wkp + 12);
            wkp += WPAD;
            ffma2(acc[0][0], A0, w0.x); ffma2(acc[0][1], A0, w0.y);
            ffma2(acc[0][2], A0, w1.x); ffma2(acc[0][3], A0, w1.y);
            ffma2(acc[0][4], A0, w2.x); ffma2(acc[0][5], A0, w2.y);
            ffma2(acc[0][6], A0, w3.x); ffma2(acc[0][7], A0, w3.y);
            ffma2(acc[1][0], A1, w0.x); ffma2(acc[1][1], A1, w0.y);
            ffma2(acc[1][2], A1, w1.x); ffma2(acc[1][3], A1, w1.y);
            ffma2(acc[1][4], A1, w2.x); ffma2(acc[1][5], A1, w2.y);
            ffma2(acc[1][6], A1, w3.x); ffma2(acc[1][7], A1, w3.y);
        }
        #pragma unroll
        for (int jp = 0; jp < 8; ++jp) {
            ulonglong2 v; v.x = acc[0][jp]; v.y = acc[1][jp];
            *reinterpret_cast<ulonglong2*>(
                &g_xw0[(((size_t)t * NJP + (j0 >> 1) + jp) * BATCH + B0 + 2 * lane) * 2]) = v;
        }
    }
}

// ============ K2': layer-0 recurrence (k=128), writes packed g_out0 ============
__global__ void __launch_bounds__(256, 1)
k_rec0(const float* __restrict__ Whh0)
{
    float* Wsm = smem;                 // [HID][WPAD]
    float* Ak  = Wsm + HID * WPAD;     // [HID][TBP]  h rows

    const int tid = threadIdx.x;
    const int B0  = blockIdx.x * TB;

    for (int d = tid; d < HID * HID; d += 256) {       // coalesced LDG, 4-way STS
        int j = d >> 7, k = d & 127;
        Wsm[k * WPAD + j] = Whh0[d];
    }
    for (int d = tid; d < HID * TB; d += 256)
        Ak[(d >> 6) * TBP + (d & 63)] = 0.0f;          // h0 = 0
    __syncthreads();

    const int wid = tid >> 5, lane = tid & 31;
    const int j0 = wid * 16;
    const float* wbase = Wsm + j0;
    const float* abase = Ak + 2 * lane;

    ulonglong2 pf[8];
    #pragma unroll
    for (int jp = 0; jp < 8; ++jp)
        pf[jp] = *reinterpret_cast<const ulonglong2*>(
            &g_xw0[(((size_t)0 * NJP + (j0 >> 1) + jp) * BATCH + B0 + 2 * lane) * 2]);

    for (int t = 0; t < TSTEPS; ++t) {
        u64 acc[2][8];
        #pragma unroll
        for (int jp = 0; jp < 8; ++jp) { acc[0][jp] = pf[jp].x; acc[1][jp] = pf[jp].y; }
        if (t + 1 < TSTEPS) {
            #pragma unroll
            for (int jp = 0; jp < 8; ++jp)
                pf[jp] = *reinterpret_cast<const ulonglong2*>(
                    &g_xw0[(((size_t)(t + 1) * NJP + (j0 >> 1) + jp) * BATCH + B0 + 2 * lane) * 2]);
        }
        const float* akp = abase;
        const float* wkp = wbase;
        GEMM16(HID, "unroll 8")
        __syncthreads();   // all h(t-1) reads done

        #pragma unroll
        for (int jp = 0; jp < 8; ++jp) {
            float v00 = fast_tanh(lo2(acc[0][jp]));   // (b0, j)
            float v01 = fast_tanh(hi2(acc[0][jp]));   // (b0, j+1)
            float v10 = fast_tanh(lo2(acc[1][jp]));   // (b1, j)
            float v11 = fast_tanh(hi2(acc[1][jp]));
            int j = j0 + 2 * jp;
            *reinterpret_cast<u64*>(&Ak[j       * TBP + 2*lane]) = pack_pair(v00, v10);
            *reinterpret_cast<u64*>(&Ak[(j + 1) * TBP + 2*lane]) = pack_pair(v01, v11);
            ulonglong2 v; v.x = pack_pair(v00, v01); v.y = pack_pair(v10, v11);
            *reinterpret_cast<ulonglong2*>(
                &g_out0[(((size_t)t * NJP + (j >> 1)) * BATCH + B0 + 2 * lane) * 2]) = v;
        }
        __syncthreads();   // h(t) visible before next GEMM
    }
}

// ============ K3: xw1 = out0 . Wih1^T + (bih1+bhh1), parallel over t ============
// 128 threads, 4 warps x 32 j, 2 CTAs/SM, 14 t per CTA
__global__ void __launch_bounds__(128)
k_ingemm1(const float* __restrict__ Wih1,
          const float* __restrict__ bih1, const float* __restrict__ bhh1)
{
    float* Wsm = smem;                 // [HID][WPAD]
    float* Ak  = Wsm + HID * WPAD;     // [HID][TBP]
    float* bs  = Ak + HID * TBP;       // HID

    const int tid = threadIdx.x;
    const int B0  = blockIdx.x * TB;

    for (int d = tid; d < HID * HID; d += 128) {
        int j = d >> 7, k = d & 127;
        Wsm[k * WPAD + j] = Wih1[d];
    }
    for (int j = tid; j < HID; j += 128) bs[j] = bih1[j] + bhh1[j];
    __syncthreads();

    const int wid = tid >> 5, lane = tid & 31;
    const int j0 = wid * 32;

    for (int tt = 0; tt < 14; ++tt) {
        const int t = blockIdx.y * 14 + tt;
        // stage out0 slice: packed (jp,b) u64 -> Ak[2jp][b], Ak[2jp+1][b]
        for (int d = tid; d < NJP * TB; d += 128) {
            int jp = d >> 6, b = d & 63;
            u64 v = *reinterpret_cast<const u64*>(
                &g_out0[(((size_t)t * NJP + jp) * BATCH + B0 + b) * 2]);
            Ak[(2*jp)     * TBP + b] = lo2(v);
            Ak[(2*jp + 1) * TBP + b] = hi2(v);
        }
        __syncthreads();

        u64 acc[2][16];
        #pragma unroll
        for (int jp = 0; jp < 16; ++jp) {
            u64 bb = pack_pair(bs[j0 + 2*jp], bs[j0 + 2*jp + 1]);
            acc[0][jp] = bb; acc[1][jp] = bb;
        }
        const float* akp = Ak + 2 * lane;
        const float* wkp = Wsm + j0;
        #pragma unroll 4
        for (int k = 0; k < HID; ++k) {
            u64 ap = *reinterpret_cast<const u64*>(akp); akp += TBP;
            u64 A0 = pack_dup(lo2(ap));
            u64 A1 = pack_dup(hi2(ap));
            #pragma unroll
            for (int m = 0; m < 4; ++m) {
                ulonglong2 wa = *reinterpret_cast<const ulonglong2*>(wkp + 8*m);
                ulonglong2 wb = *reinterpret_cast<const ulonglong2*>(wkp + 8*m + 4);
                ffma2(acc[0][4*m+0], A0, wa.x); ffma2(acc[0][4*m+1], A0, wa.y);
                ffma2(acc[0][4*m+2], A0, wb.x); ffma2(acc[0][4*m+3], A0, wb.y);
                ffma2(acc[1][4*m+0], A1, wa.x); ffma2(acc[1][4*m+1], A1, wa.y);
                ffma2(acc[1][4*m+2], A1, wb.x); ffma2(acc[1][4*m+3], A1, wb.y);
            }
            wkp += WPAD;
        }
        #pragma unroll
        for (int jp = 0; jp < 16; ++jp) {
            ulonglong2 v; v.x = acc[0][jp]; v.y = acc[1][jp];
            *reinterpret_cast<ulonglong2*>(
                &g_xw1[(((size_t)t * NJP + (j0 >> 1) + jp) * BATCH + B0 + 2 * lane) * 2]) = v;
        }
        __syncthreads();   // Ak reads done before next-t staging
    }
}

// ============ K4: layer-1 recurrence + FC head ============
__global__ void __launch_bounds__(256, 1)
k_rec1_fc(const float* __restrict__ Whh1,
          const float* __restrict__ fcw, const float* __restrict__ fcb,
          float* __restrict__ out)
{
    float* Wsm  = smem;                 // [HID][WPAD]
    float* Ak   = Wsm + HID * WPAD;     // [HID][TBP]
    float* fcs  = Ak + HID * TBP;       // 10*HID
    float* fcbs = fcs + 10 * HID;       // 16

    const int tid = threadIdx.x;
    const int B0  = blockIdx.x * TB;

    for (int d = tid; d < HID * HID; d += 256) {
        int j = d >> 7, k = d & 127;
        Wsm[k * WPAD + j] = Whh1[d];
    }
    for (int d = tid; d < 10 * HID; d += 256) fcs[d] = fcw[d];
    if (tid < 10) fcbs[tid] = fcb[tid];
    for (int d = tid; d < HID * TB; d += 256)
        Ak[(d >> 6) * TBP + (d & 63)] = 0.0f;
    __syncthreads();

    const int wid = tid >> 5, lane = tid & 31;
    const int j0 = wid * 16;
    const float* wbase = Wsm + j0;
    const float* abase = Ak + 2 * lane;

    ulonglong2 pf[8];
    #pragma unroll
    for (int jp = 0; jp < 8; ++jp)
        pf[jp] = *reinterpret_cast<const ulonglong2*>(
            &g_xw1[(((size_t)0 * NJP + (j0 >> 1) + jp) * BATCH + B0 + 2 * lane) * 2]);

    for (int t = 0; t < TSTEPS; ++t) {
        u64 acc[2][8];
        #pragma unroll
        for (int jp = 0; jp < 8; ++jp) { acc[0][jp] = pf[jp].x; acc[1][jp] = pf[jp].y; }
        if (t + 1 < TSTEPS) {
            #pragma unroll
            for (int jp = 0; jp < 8; ++jp)
                pf[jp] = *reinterpret_cast<const ulonglong2*>(
                    &g_xw1[(((size_t)(t + 1) * NJP + (j0 >> 1) + jp) * BATCH + B0 + 2 * lane) * 2]);
        }
        const float* akp = abase;
        const float* wkp = wbase;
        GEMM16(HID, "unroll 8")
        __syncthreads();

        #pragma unroll
        for (int jp = 0; jp < 8; ++jp) {
            float v00 = fast_tanh(lo2(acc[0][jp]));
            float v01 = fast_tanh(hi2(acc[0][jp]));
            float v10 = fast_tanh(lo2(acc[1][jp]));
            float v11 = fast_tanh(hi2(acc[1][jp]));
            int j = j0 + 2 * jp;
            *reinterpret_cast<u64*>(&Ak[j       * TBP + 2*lane]) = pack_pair(v00, v10);
            *reinterpret_cast<u64*>(&Ak[(j + 1) * TBP + 2*lane]) = pack_pair(v01, v11);
        }
        __syncthreads();
    }

    // FC head
    for (int o = tid; o < TB * 10; o += 256) {
        int b = o / 10, c = o - b * 10;
        const float* wv = &fcs[c * HID];
        float s = fcbs[c];
        #pragma unroll 8
        for (int k = 0; k < HID; ++k)
            s = fmaf(Ak[k * TBP + b], wv[k], s);
        out[(size_t)(B0 + b) * 10 + c] = s;
    }
}

extern "C" void kernel_launch(void* const* d_in, const int* in_sizes, int n_in,
                              void* d_out, int out_size) {
    const float* x     = (const float*)d_in[0];
    const float* Wih0  = (const float*)d_in[1];
    const float* Whh0  = (const float*)d_in[2];
    const float* bih0  = (const float*)d_in[3];
    const float* bhh0  = (const float*)d_in[4];
    const float* Wih1  = (const float*)d_in[5];
    const float* Whh1  = (const float*)d_in[6];
    const float* bih1  = (const float*)d_in[7];
    const float* bhh1  = (const float*)d_in[8];
    const float* fcw   = (const float*)d_in[9];
    const float* fcb   = (const float*)d_in[10];
    float* out = (float*)d_out;

    const int smem1 = (INP * WPAD + HID) * 4;                          // ~15 KB
    const int smemR0 = (HID * WPAD + HID * TBP) * 4;                   // ~101 KB
    const int smem3 = (HID * WPAD + HID * TBP + HID) * 4;              // ~102 KB (2/SM)
    const int smemR1 = (HID * WPAD + HID * TBP + 10 * HID + 16) * 4;   // ~107 KB
    cudaFuncSetAttribute(k_ingemm0, cudaFuncAttributeMaxDynamicSharedMemorySize, smem1);
    cudaFuncSetAttribute(k_rec0,    cudaFuncAttributeMaxDynamicSharedMemorySize, smemR0);
    cudaFuncSetAttribute(k_ingemm1, cudaFuncAttributeMaxDynamicSharedMemorySize, smem3);
    cudaFuncSetAttribute(k_rec1_fc, cudaFuncAttributeMaxDynamicSharedMemorySize, smemR1);

    const int gridB = BATCH / TB;   // 128
    k_ingemm0<<<dim3(gridB, 4), 256, smem1>>>(x, Wih0, bih0, bhh0);
    k_rec0   <<<gridB, 256, smemR0>>>(Whh0);
    k_ingemm1<<<dim3(gridB, 2), 128, smem3>>>(Wih1, bih1, bhh1);
    k_rec1_fc<<<gridB, 256, smemR1>>>(Whh1, fcw, fcb, out);
}

// round 17
// speedup vs baseline: 1.4173x; 1.0812x over previous
#include <cuda_runtime.h>
#include <cstdint>

#define TB      64
#define HID     128
#define TSTEPS  28
#define INP     28
#define BATCH   8192
#define TBP     66      // Ak row pad (≡2 mod 32 -> conflict-free LDS/STS.64)
#define WPAD    132     // weight row pad (≡4 mod 32; rows 16B-aligned)
#define NJP     64      // j-pairs

// acc-packed interchange buffers: [t][jp][B][2]
__device__ __align__(16) float g_xw0 [(size_t)TSTEPS * NJP * BATCH * 2];
__device__ __align__(16) float g_out0[(size_t)TSTEPS * NJP * BATCH * 2];
__device__ __align__(16) float g_xw1 [(size_t)TSTEPS * NJP * BATCH * 2];

typedef unsigned long long u64;

__device__ __forceinline__ u64 pack_dup(float a) {
    u64 r; asm("mov.b64 %0, {%1, %1};" : "=l"(r) : "r"(__float_as_uint(a))); return r;
}
__device__ __forceinline__ u64 pack_pair(float lo, float hi) {
    u64 r; asm("mov.b64 %0, {%1, %2};" : "=l"(r) : "r"(__float_as_uint(lo)), "r"(__float_as_uint(hi))); return r;
}
__device__ __forceinline__ void ffma2(u64& d, u64 a, u64 b) {
    asm("fma.rn.f32x2 %0, %1, %2, %0;" : "+l"(d) : "l"(a), "l"(b));
}
__device__ __forceinline__ float lo2(u64 v) { return __uint_as_float((unsigned)v); }
__device__ __forceinline__ float hi2(u64 v) { return __uint_as_float((unsigned)(v >> 32)); }

__device__ __forceinline__ float fast_tanh(float x) {
    float e = __expf(2.0f * x);
    return 1.0f - __fdividef(2.0f, e + 1.0f);
}

extern __shared__ float smem[];

// 16-j warps (8 warps, 256 thr): per k 1 LDS.64 + 4 uniform LDS.128 + 16 FFMA2
#define GEMM16(KK, UNR)                                                         \
    _Pragma(UNR)                                                                \
    for (int k = 0; k < KK; ++k) {                                              \
        u64 ap = *reinterpret_cast<const u64*>(akp); akp += TBP;                \
        u64 A0 = pack_dup(lo2(ap));                                             \
        u64 A1 = pack_dup(hi2(ap));                                             \
        ulonglong2 w0 = *reinterpret_cast<const ulonglong2*>(wkp);              \
        ulonglong2 w1 = *reinterpret_cast<const ulonglong2*>(wkp + 4);          \
        ulonglong2 w2 = *reinterpret_cast<const ulonglong2*>(wkp + 8);          \
        ulonglong2 w3 = *reinterpret_cast<const ulonglong2*>(wkp + 12);         \
        wkp += WPAD;                                                            \
        ffma2(acc[0][0], A0, w0.x); ffma2(acc[0][1], A0, w0.y);                 \
        ffma2(acc[0][2], A0, w1.x); ffma2(acc[0][3], A0, w1.y);                 \
        ffma2(acc[0][4], A0, w2.x); ffma2(acc[0][5], A0, w2.y);                 \
        ffma2(acc[0][6], A0, w3.x); ffma2(acc[0][7], A0, w3.y);                 \
        ffma2(acc[1][0], A1, w0.x); ffma2(acc[1][1], A1, w0.y);                 \
        ffma2(acc[1][2], A1, w1.x); ffma2(acc[1][3], A1, w1.y);                 \
        ffma2(acc[1][4], A1, w2.x); ffma2(acc[1][5], A1, w2.y);                 \
        ffma2(acc[1][6], A1, w3.x); ffma2(acc[1][7], A1, w3.y);                 \
    }

// ============ K1: xw0 = x . Wih0^T + (bih0+bhh0), parallel over t ============
__global__ void __launch_bounds__(256)
k_ingemm0(const float* __restrict__ x, const float* __restrict__ Wih0,
          const float* __restrict__ bih0, const float* __restrict__ bhh0)
{
    float* Wsm = smem;                 // [INP][WPAD]
    float* bs  = Wsm + INP * WPAD;     // HID

    const int tid = threadIdx.x;
    const int B0  = blockIdx.x * TB;

    for (int d = tid; d < HID * INP; d += 256) {
        int j = d / INP, k = d - j * INP;
        Wsm[k * WPAD + j] = Wih0[d];
    }
    for (int j = tid; j < HID; j += 256) bs[j] = bih0[j] + bhh0[j];
    __syncthreads();

    const int wid = tid >> 5, lane = tid & 31;
    const int j0 = wid * 16;

    for (int tt = 0; tt < 7; ++tt) {
        const int t = blockIdx.y * 7 + tt;
        float xr0[INP], xr1[INP];
        const float* xp0 = x + (size_t)(B0 + 2 * lane) * (TSTEPS * INP) + t * INP;
        const float* xp1 = xp0 + TSTEPS * INP;
        #pragma unroll
        for (int i = 0; i < INP; ++i) { xr0[i] = xp0[i]; xr1[i] = xp1[i]; }

        u64 acc[2][8];
        #pragma unroll
        for (int jp = 0; jp < 8; ++jp) {
            u64 bb = pack_pair(bs[j0 + 2*jp], bs[j0 + 2*jp + 1]);
            acc[0][jp] = bb; acc[1][jp] = bb;
        }
        const float* wkp = Wsm + j0;
        #pragma unroll
        for (int k = 0; k < INP; ++k) {
            u64 A0 = pack_dup(xr0[k]);
            u64 A1 = pack_dup(xr1[k]);
            ulonglong2 w0 = *reinterpret_cast<const ulonglong2*>(wkp);
            ulonglong2 w1 = *reinterpret_cast<const ulonglong2*>(wkp + 4);
            ulonglong2 w2 = *reinterpret_cast<const ulonglong2*>(wkp + 8);
            ulonglong2 w3 = *reinterpret_cast<const ulonglong2*>(wkp + 12);
            wkp += WPAD;
            ffma2(acc[0][0], A0, w0.x); ffma2(acc[0][1], A0, w0.y);
            ffma2(acc[0][2], A0, w1.x); ffma2(acc[0][3], A0, w1.y);
            ffma2(acc[0][4], A0, w2.x); ffma2(acc[0][5], A0, w2.y);
            ffma2(acc[0][6], A0, w3.x); ffma2(acc[0][7], A0, w3.y);
            ffma2(acc[1][0], A1, w0.x); ffma2(acc[1][1], A1, w0.y);
            ffma2(acc[1][2], A1, w1.x); ffma2(acc[1][3], A1, w1.y);
            ffma2(acc[1][4], A1, w2.x); ffma2(acc[1][5], A1, w2.y);
            ffma2(acc[1][6], A1, w3.x); ffma2(acc[1][7], A1, w3.y);
        }
        #pragma unroll
        for (int jp = 0; jp < 8; ++jp) {
            ulonglong2 v; v.x = acc[0][jp]; v.y = acc[1][jp];
            *reinterpret_cast<ulonglong2*>(
                &g_xw0[(((size_t)t * NJP + (j0 >> 1) + jp) * BATCH + B0 + 2 * lane) * 2]) = v;
        }
    }
}

// ============ K2': layer-0 recurrence (k=128), double-buffered h ============
__global__ void __launch_bounds__(256, 1)
k_rec0(const float* __restrict__ Whh0)
{
    float* Wsm = smem;                 // [HID][WPAD]
    float* Ak0 = Wsm + HID * WPAD;     // [HID][TBP]  h buffer 0
    float* Ak1 = Ak0 + HID * TBP;      // h buffer 1

    const int tid = threadIdx.x;
    const int B0  = blockIdx.x * TB;

    for (int d = tid; d < HID * HID; d += 256) {
        int j = d >> 7, k = d & 127;
        Wsm[k * WPAD + j] = Whh0[d];
    }
    for (int d = tid; d < HID * TB; d += 256)
        Ak0[(d >> 6) * TBP + (d & 63)] = 0.0f;          // h0 = 0 (t=0 reads buf0)
    __syncthreads();

    const int wid = tid >> 5, lane = tid & 31;
    const int j0 = wid * 16;
    const float* wbase = Wsm + j0;
    float* buf[2] = {Ak0, Ak1};

    ulonglong2 pf[8];
    #pragma unroll
    for (int jp = 0; jp < 8; ++jp)
        pf[jp] = *reinterpret_cast<const ulonglong2*>(
            &g_xw0[(((size_t)0 * NJP + (j0 >> 1) + jp) * BATCH + B0 + 2 * lane) * 2]);

    for (int t = 0; t < TSTEPS; ++t) {
        u64 acc[2][8];
        #pragma unroll
        for (int jp = 0; jp < 8; ++jp) { acc[0][jp] = pf[jp].x; acc[1][jp] = pf[jp].y; }
        if (t + 1 < TSTEPS) {
            #pragma unroll
            for (int jp = 0; jp < 8; ++jp)
                pf[jp] = *reinterpret_cast<const ulonglong2*>(
                    &g_xw0[(((size_t)(t + 1) * NJP + (j0 >> 1) + jp) * BATCH + B0 + 2 * lane) * 2]);
        }
        const float* akp = buf[t & 1] + 2 * lane;
        const float* wkp = wbase;
        GEMM16(HID, "unroll 8")

        float* wb = buf[(t & 1) ^ 1];   // write h(t) into the other buffer
        #pragma unroll
        for (int jp = 0; jp < 8; ++jp) {
            float v00 = fast_tanh(lo2(acc[0][jp]));   // (b0, j)
            float v01 = fast_tanh(hi2(acc[0][jp]));   // (b0, j+1)
            float v10 = fast_tanh(lo2(acc[1][jp]));   // (b1, j)
            float v11 = fast_tanh(hi2(acc[1][jp]));
            int j = j0 + 2 * jp;
            *reinterpret_cast<u64*>(&wb[j       * TBP + 2*lane]) = pack_pair(v00, v10);
            *reinterpret_cast<u64*>(&wb[(j + 1) * TBP + 2*lane]) = pack_pair(v01, v11);
            ulonglong2 v; v.x = pack_pair(v00, v01); v.y = pack_pair(v10, v11);
            *reinterpret_cast<ulonglong2*>(
                &g_out0[(((size_t)t * NJP + (j >> 1)) * BATCH + B0 + 2 * lane) * 2]) = v;
        }
        __syncthreads();   // publish h(t); reads of buf[t&1] already done per-warp
    }
}

// ============ K3: xw1 = out0 . Wih1^T + (bih1+bhh1), parallel over t ============
// 256 threads, 8 warps x 16 j, 2 CTAs/SM, 7 t per CTA
__global__ void __launch_bounds__(256, 2)
k_ingemm1(const float* __restrict__ Wih1,
          const float* __restrict__ bih1, const float* __restrict__ bhh1)
{
    float* Wsm = smem;                 // [HID][WPAD]
    float* Ak  = Wsm + HID * WPAD;     // [HID][TBP]
    float* bs  = Ak + HID * TBP;       // HID

    const int tid = threadIdx.x;
    const int B0  = blockIdx.x * TB;

    for (int d = tid; d < HID * HID; d += 256) {
        int j = d >> 7, k = d & 127;
        Wsm[k * WPAD + j] = Wih1[d];
    }
    for (int j = tid; j < HID; j += 256) bs[j] = bih1[j] + bhh1[j];
    __syncthreads();

    const int wid = tid >> 5, lane = tid & 31;
    const int j0 = wid * 16;

    for (int tt = 0; tt < 7; ++tt) {
        const int t = blockIdx.y * 7 + tt;
        // stage out0 slice: packed (jp,b) u64 -> Ak[2jp][b], Ak[2jp+1][b]
        for (int d = tid; d < NJP * TB; d += 256) {
            int jp = d >> 6, b = d & 63;
            u64 v = *reinterpret_cast<const u64*>(
                &g_out0[(((size_t)t * NJP + jp) * BATCH + B0 + b) * 2]);
            Ak[(2*jp)     * TBP + b] = lo2(v);
            Ak[(2*jp + 1) * TBP + b] = hi2(v);
        }
        __syncthreads();

        u64 acc[2][8];
        #pragma unroll
        for (int jp = 0; jp < 8; ++jp) {
            u64 bb = pack_pair(bs[j0 + 2*jp], bs[j0 + 2*jp + 1]);
            acc[0][jp] = bb; acc[1][jp] = bb;
        }
        const float* akp = Ak + 2 * lane;
        const float* wkp = Wsm + j0;
        GEMM16(HID, "unroll 4")

        #pragma unroll
        for (int jp = 0; jp < 8; ++jp) {
            ulonglong2 v; v.x = acc[0][jp]; v.y = acc[1][jp];
            *reinterpret_cast<ulonglong2*>(
                &g_xw1[(((size_t)t * NJP + (j0 >> 1) + jp) * BATCH + B0 + 2 * lane) * 2]) = v;
        }
        __syncthreads();   // Ak reads done before next-t staging
    }
}

// ============ K4: layer-1 recurrence + FC head, double-buffered h ============
__global__ void __launch_bounds__(256, 1)
k_rec1_fc(const float* __restrict__ Whh1,
          const float* __restrict__ fcw, const float* __restrict__ fcb,
          float* __restrict__ out)
{
    float* Wsm  = smem;                 // [HID][WPAD]
    float* Ak0  = Wsm + HID * WPAD;     // h buffer 0
    float* Ak1  = Ak0 + HID * TBP;      // h buffer 1
    float* fcs  = Ak1 + HID * TBP;      // 10*HID
    float* fcbs = fcs + 10 * HID;       // 16

    const int tid = threadIdx.x;
    const int B0  = blockIdx.x * TB;

    for (int d = tid; d < HID * HID; d += 256) {
        int j = d >> 7, k = d & 127;
        Wsm[k * WPAD + j] = Whh1[d];
    }
    for (int d = tid; d < 10 * HID; d += 256) fcs[d] = fcw[d];
    if (tid < 10) fcbs[tid] = fcb[tid];
    for (int d = tid; d < HID * TB; d += 256)
        Ak0[(d >> 6) * TBP + (d & 63)] = 0.0f;
    __syncthreads();

    const int wid = tid >> 5, lane = tid & 31;
    const int j0 = wid * 16;
    const float* wbase = Wsm + j0;
    float* buf[2] = {Ak0, Ak1};

    ulonglong2 pf[8];
    #pragma unroll
    for (int jp = 0; jp < 8; ++jp)
        pf[jp] = *reinterpret_cast<const ulonglong2*>(
            &g_xw1[(((size_t)0 * NJP + (j0 >> 1) + jp) * BATCH + B0 + 2 * lane) * 2]);

    for (int t = 0; t < TSTEPS; ++t) {
        u64 acc[2][8];
        #pragma unroll
        for (int jp = 0; jp < 8; ++jp) { acc[0][jp] = pf[jp].x; acc[1][jp] = pf[jp].y; }
        if (t + 1 < TSTEPS) {
            #pragma unroll
            for (int jp = 0; jp < 8; ++jp)
                pf[jp] = *reinterpret_cast<const ulonglong2*>(
                    &g_xw1[(((size_t)(t + 1) * NJP + (j0 >> 1) + jp) * BATCH + B0 + 2 * lane) * 2]);
        }
        const float* akp = buf[t & 1] + 2 * lane;
        const float* wkp = wbase;
        GEMM16(HID, "unroll 8")

        float* wb = buf[(t & 1) ^ 1];
        #pragma unroll
        for (int jp = 0; jp < 8; ++jp) {
            float v00 = fast_tanh(lo2(acc[0][jp]));
            float v01 = fast_tanh(hi2(acc[0][jp]));
            float v10 = fast_tanh(lo2(acc[1][jp]));
            float v11 = fast_tanh(hi2(acc[1][jp]));
            int j = j0 + 2 * jp;
            *reinterpret_cast<u64*>(&wb[j       * TBP + 2*lane]) = pack_pair(v00, v10);
            *reinterpret_cast<u64*>(&wb[(j + 1) * TBP + 2*lane]) = pack_pair(v01, v11);
        }
        __syncthreads();
    }

    // FC head: h(27) lives in buf[(27+1)&1] = buf0
    const float* hb = buf[TSTEPS & 1];
    for (int o = tid; o < TB * 10; o += 256) {
        int b = o / 10, c = o - b * 10;
        const float* wv = &fcs[c * HID];
        float s = fcbs[c];
        #pragma unroll 8
        for (int k = 0; k < HID; ++k)
            s = fmaf(hb[k * TBP + b], wv[k], s);
        out[(size_t)(B0 + b) * 10 + c] = s;
    }
}

extern "C" void kernel_launch(void* const* d_in, const int* in_sizes, int n_in,
                              void* d_out, int out_size) {
    const float* x     = (const float*)d_in[0];
    const float* Wih0  = (const float*)d_in[1];
    const float* Whh0  = (const float*)d_in[2];
    const float* bih0  = (const float*)d_in[3];
    const float* bhh0  = (const float*)d_in[4];
    const float* Wih1  = (const float*)d_in[5];
    const float* Whh1  = (const float*)d_in[6];
    const float* bih1  = (const float*)d_in[7];
    const float* bhh1  = (const float*)d_in[8];
    const float* fcw   = (const float*)d_in[9];
    const float* fcb   = (const float*)d_in[10];
    float* out = (float*)d_out;

    const int smem1  = (INP * WPAD + HID) * 4;                               // ~15 KB
    const int smemR0 = (HID * WPAD + 2 * HID * TBP) * 4;                     // ~135 KB
    const int smem3  = (HID * WPAD + HID * TBP + HID) * 4;                   // ~102 KB (2/SM)
    const int smemR1 = (HID * WPAD + 2 * HID * TBP + 10 * HID + 16) * 4;     // ~140 KB
    cudaFuncSetAttribute(k_ingemm0, cudaFuncAttributeMaxDynamicSharedMemorySize, smem1);
    cudaFuncSetAttribute(k_rec0,    cudaFuncAttributeMaxDynamicSharedMemorySize, smemR0);
    cudaFuncSetAttribute(k_ingemm1, cudaFuncAttributeMaxDynamicSharedMemorySize, smem3);
    cudaFuncSetAttribute(k_rec1_fc, cudaFuncAttributeMaxDynamicSharedMemorySize, smemR1);

    const int gridB = BATCH / TB;   // 128
    k_ingemm0<<<dim3(gridB, 4), 256, smem1>>>(x, Wih0, bih0, bhh0);
    k_rec0   <<<gridB, 256, smemR0>>>(Whh0);
    k_ingemm1<<<dim3(gridB, 4), 256, smem3>>>(Wih1, bih1, bhh1);
    k_rec1_fc<<<gridB, 256, smemR1>>>(Whh1, fcw, fcb, out);
}